// round 9
// baseline (speedup 1.0000x reference)
#include <cuda_runtime.h>
#include <cstdint>
#include <math.h>

// Problem constants (fixed by the reference setup)
#define BATCH 64
#define QN    900
#define CN    365
#define MN    (BATCH * QN)          // 57600 rows

// Output layout in d_out (float32, tuple order: scores, boxes_int, keep)
#define OFF_BOX  (MN * CN)          // 21,024,000
#define OFF_KEEP (OFF_BOX + MN * 4) // 21,254,400

#define NVCAP 512                   // max valid entries per image (mean ~247, ~20 sigma margin)
#define MASKW 8                     // 512/64 suppression mask words

// -------- device scratch (no allocations allowed, no per-replay reset needed) --------
__device__ int      g_rows[BATCH * NVCAP];  // per-batch kept row indices
__device__ int      g_cnt [BATCH];          // per-batch kept count
__device__ unsigned g_Bh[CN * CN];          // Aaug tf32-hi (precomputed each launch)
__device__ unsigned g_Bl[CN * CN];          // Aaug tf32-lo

// ---- cp.async helpers (4-byte, src-size-0 form zero-fills out-of-bounds) ----
__device__ __forceinline__ void cp_async4(unsigned int dst_smem, const void* src, int szsrc) {
    asm volatile("cp.async.ca.shared.global [%0], [%1], 4, %2;\n"
                 :: "r"(dst_smem), "l"(src), "r"(szsrc));
}
#define CP_COMMIT() asm volatile("cp.async.commit_group;\n" ::: "memory")
#define CP_WAIT0()  asm volatile("cp.async.wait_group 0;\n" ::: "memory")

// ---- tf32 helpers ----
__device__ __forceinline__ unsigned int f2tf32(float x) {
    unsigned int r;
    asm("cvt.rna.tf32.f32 %0, %1;" : "=r"(r) : "f"(x));
    return r;
}

#define MMA_TF32(d0,d1,d2,d3, a0,a1,a2,a3, b0,b1)                          \
    asm volatile("mma.sync.aligned.m16n8k8.row.col.f32.tf32.tf32.f32 "     \
                 "{%0,%1,%2,%3}, {%4,%5,%6,%7}, {%8,%9}, {%0,%1,%2,%3};\n" \
                 : "+f"(d0), "+f"(d1), "+f"(d2), "+f"(d3)                  \
                 : "r"(a0), "r"(a1), "r"(a2), "r"(a3), "r"(b0), "r"(b1))

// ============================================================
// Kernel 1: blocks [0,64): per-image prep + NMS
//           blocks [64, 64+1024): zero the scores region
//           blocks [64+1024, 64+1024+261): split Aaug into g_Bh/g_Bl
// ============================================================
#define NMS_THREADS 512
#define ZBLK 1024
#define CBLK 261                        // ceil(365*365 / 512)
// dynamic smem layout (bytes)
#define SB_BOXO  0                      // float4[900] : 14400
#define SB_SCORE 14400                  // float[900]  : 3600
#define SB_LIST  18000                  // int[512]    : 2048
#define SB_KEY   20048                  // float[512]  : 2048
#define SB_BOXS  22096                  // float4[512] : 8192
#define SB_MASK  30288                  // u64[512*8]  : 32768
#define SB_KP    63056                  // u8[512]     : 512
#define SB_CNT   63568                  // int         : 4
#define SB_TOTAL 63576

__global__ void __launch_bounds__(NMS_THREADS, 1)
nms_zero_kernel(const float* __restrict__ human,
                const float* __restrict__ bbox,
                const float* __restrict__ Aaug,
                float* __restrict__ out)
{
    int t = threadIdx.x;

    // ---------- Aaug tf32-split blocks ----------
    if (blockIdx.x >= BATCH + ZBLK) {
        int i = (blockIdx.x - (BATCH + ZBLK)) * NMS_THREADS + t;
        if (i < CN * CN) {
            float v = Aaug[i];
            unsigned hi = f2tf32(v);
            g_Bh[i] = hi;
            g_Bl[i] = f2tf32(v - __uint_as_float(hi));
        }
        return;
    }

    // ---------- zero-fill blocks ----------
    if (blockIdx.x >= BATCH) {
        const size_t total4 = (size_t)MN * CN / 4;
        float4 z = make_float4(0.f, 0.f, 0.f, 0.f);
        size_t stride = (size_t)ZBLK * NMS_THREADS;
        for (size_t p = (size_t)(blockIdx.x - BATCH) * NMS_THREADS + t;
             p < total4; p += stride)
            reinterpret_cast<float4*>(out)[p] = z;
        return;
    }

    // ---------- NMS blocks: one image each ----------
    extern __shared__ unsigned char sm[];
    float4*             sboxO  = (float4*)(sm + SB_BOXO);
    float*              sscore = (float*) (sm + SB_SCORE);
    int*                slist  = (int*)   (sm + SB_LIST);
    float*              skey   = (float*) (sm + SB_KEY);
    float4*             sboxS  = (float4*)(sm + SB_BOXS);
    unsigned long long* smask  = (unsigned long long*)(sm + SB_MASK);
    unsigned char*      skp    = sm + SB_KP;
    int*                scnt   = (int*)   (sm + SB_CNT);

    int b = blockIdx.x;
    int base = b * QN;
    float4* outBox4 = reinterpret_cast<float4*>(out + OFF_BOX);

    // Phase A: per-query prep
    if (t == 0) *scnt = 0;
    for (int q = t; q < QN; q += NMS_THREADS) {
        float2 h = reinterpret_cast<const float2*>(human)[base + q];
        float d = h.x - h.y;
        float p = 1.0f / (1.0f + expf(-fabsf(d)));   // max softmax prob
        bool valid = (d >= 0.0f) && (p >= 0.7f);     // label==0 && conf

        float4 bb = reinterpret_cast<const float4*>(bbox)[base + q];
        float x1 = (bb.x - 0.5f * bb.z) * 1333.0f;
        float y1 = (bb.y - 0.5f * bb.w) * 800.0f;
        float x2 = (bb.x + 0.5f * bb.z) * 1333.0f;
        float y2 = (bb.y + 0.5f * bb.w) * 800.0f;
        sboxO[q]  = make_float4(x1, y1, x2, y2);
        sscore[q] = valid ? p : -INFINITY;

        outBox4[base + q] = make_float4((float)(int)x1, (float)(int)y1,
                                        (float)(int)x2, (float)(int)y2);
        out[OFF_KEEP + base + q] = 0.0f;
    }
    __syncthreads();

    // Phase B: compact valid queries
    for (int q = t; q < QN; q += NMS_THREADS) {
        if (sscore[q] != -INFINITY) {
            int pos = atomicAdd(scnt, 1);
            if (pos < NVCAP) slist[pos] = q;
        }
    }
    __syncthreads();
    int nv = min(*scnt, NVCAP);

    // Phase C: bitonic sort (key desc, carry original q index)
    skey[t] = (t < nv) ? sscore[slist[t]] : -INFINITY;
    if (t >= nv) slist[t] = 0;
    skp[t] = 0;
    __syncthreads();
    for (int k = 2; k <= NVCAP; k <<= 1) {
        for (int j = k >> 1; j > 0; j >>= 1) {
            int ixj = t ^ j;
            if (ixj > t) {
                bool desc = ((t & k) == 0);
                float k1 = skey[t], k2 = skey[ixj];
                if (desc ? (k1 < k2) : (k1 > k2)) {
                    skey[t] = k2; skey[ixj] = k1;
                    int tmp = slist[t]; slist[t] = slist[ixj]; slist[ixj] = tmp;
                }
            }
            __syncthreads();
        }
    }

    // Phase D: gather boxes into sorted order
    if (t < nv) sboxS[t] = sboxO[slist[t]];
    __syncthreads();

    // Phase E: IoU suppression bitmask
    int nw = (nv + 63) >> 6;
    for (int flat = t; flat < nv * nw; flat += NMS_THREADS) {
        int i = flat / nw;
        int w = flat - i * nw;
        int jbase = w << 6;
        unsigned long long bits = 0ull;
        int jstart = max(jbase, i + 1);
        int jend   = min(jbase + 63, nv - 1);
        if (jstart <= jend) {
            float4 bi = sboxS[i];
            float areai = (bi.z - bi.x) * (bi.w - bi.y);
            for (int j = jstart; j <= jend; j++) {
                float4 bj = sboxS[j];
                float xx1 = fmaxf(bi.x, bj.x);
                float yy1 = fmaxf(bi.y, bj.y);
                float xx2 = fminf(bi.z, bj.z);
                float yy2 = fminf(bi.w, bj.w);
                float ww = fmaxf(xx2 - xx1, 0.0f);
                float hh = fmaxf(yy2 - yy1, 0.0f);
                float inter = ww * hh;
                float areaj = (bj.z - bj.x) * (bj.w - bj.y);
                float uni = fmaxf(areai + areaj - inter, 1e-9f);
                if (inter > 0.5f * uni) bits |= (1ull << (j - jbase));
            }
        }
        smask[i * MASKW + w] = bits;
    }
    __syncthreads();

    // Phase F: sequential greedy scan
    if (t < 32) {
        unsigned long long remv = 0ull;
        for (int i = 0; i < nv; i++) {
            unsigned long long word = __shfl_sync(0xffffffffu, remv, i >> 6);
            bool sup = (word >> (i & 63)) & 1ull;
            if (!sup) {
                if (t == 0) skp[i] = 1;
                if (t < nw) remv |= smask[i * MASKW + t];
            }
        }
    }
    __syncthreads();

    // Phase G: outputs
    if (t == 0) *scnt = 0;
    __syncthreads();
    if (t < nv && skp[t]) {
        out[OFF_KEEP + base + slist[t]] = 1.0f;
        int pos = atomicAdd(scnt, 1);
        g_rows[b * NVCAP + pos] = base + slist[t];
    }
    __syncthreads();
    if (t == 0) g_cnt[b] = *scnt;
}

// ============================================================
// Kernel 2: prob = logits[kept rows] @ Aaug via 3xTF32 mma.sync
// A raw cp.async double-buffered, split once per tile (block-wide pass);
// B pre-split (g_Bh/g_Bl) cp.async'd directly. No in-loop conversions.
// fused epilogue: scores = (prob>=0.25) ? (prob+1)*0.5 : 0
// ============================================================
#define GBM 128
#define GBN 128
#define GBK 16
#define AST 20                      // A smem k-stride (conflict-free for frag loads)
#define BST 136                     // B smem n-stride (conflict-free for frag loads)
#define NT_TILES 23                 // ceil(365/16)

// dynamic smem layout (bytes)
#define GB_AR   0                       // float [2][128][20] : 20480
#define GB_AH   20480                   // uint  [128][20]    : 10240
#define GB_AL   30720                   // uint  [128][20]    : 10240
#define GB_BH   40960                   // uint  [2][16][136] : 17408
#define GB_BL   58368                   // uint  [2][16][136] : 17408
#define GB_ROWS 75776                   // int   [128]        : 512
#define GB_TOTAL 76288

__global__ void __launch_bounds__(256, 2)
gemm_epi_kernel(const float* __restrict__ A,   // [MN, 365]
                float* __restrict__ out)
{
    extern __shared__ unsigned char sm[];
    float*    smAr  = (float*)   (sm + GB_AR);   // [2][128][AST]
    unsigned* smAh  = (unsigned*)(sm + GB_AH);   // [128][AST]
    unsigned* smAl  = (unsigned*)(sm + GB_AL);
    unsigned* smBh  = (unsigned*)(sm + GB_BH);   // [2][16][BST]
    unsigned* smBl  = (unsigned*)(sm + GB_BL);
    int*      rows_s = (int*)    (sm + GB_ROWS);

    const int K = CN, N = CN;
    int bz  = blockIdx.z;
    int cnt = g_cnt[bz];
    int m0  = blockIdx.y * GBM;
    if (m0 >= cnt) return;
    int n0 = blockIdx.x * GBN;

    int t    = threadIdx.x;
    int lane = t & 31;
    int gid  = lane >> 2;           // 0..7
    int tig  = lane & 3;            // 0..3
    int warp = t >> 5;
    int wM   = warp >> 2;           // 0..1  -> 64 m-rows each
    int wN   = warp & 3;            // 0..3  -> 32 n-cols each

    if (t < GBM) {
        int mi = m0 + t;
        rows_s[t] = g_rows[bz * NVCAP + (mi < cnt ? mi : cnt - 1)];
    }
    __syncthreads();

    // ---- async tile loader: raw A + pre-split Bh/Bl ----
    auto load_tile = [&](int buf, int k0) {
#pragma unroll
        for (int u = 0; u < 8; u++) {               // A: e -> (m=e>>4, k=e&15)
            int e = t + u * 256;
            int m = e >> 4, k = e & 15;
            int kk = k0 + k;
            int sz = (kk < K) ? 4 : 0;
            int kc = (kk < K) ? kk : (K - 1);
            unsigned int dst = (unsigned int)__cvta_generic_to_shared(
                &smAr[buf * GBM * AST + m * AST + k]);
            cp_async4(dst, A + (size_t)rows_s[m] * K + kc, sz);
        }
#pragma unroll
        for (int u = 0; u < 8; u++) {               // B: e -> (k=e>>7, n=e&127)
            int e = t + u * 256;
            int k = e >> 7, n = e & 127;
            int kk = k0 + k, nn = n0 + n;
            int sz = (kk < K && nn < N) ? 4 : 0;
            int kc = (kk < K) ? kk : (K - 1);
            int nc = (nn < N) ? nn : (N - 1);
            int so = buf * GBK * BST + k * BST + n;
            int go = kc * N + nc;
            unsigned int dh = (unsigned int)__cvta_generic_to_shared(&smBh[so]);
            unsigned int dl = (unsigned int)__cvta_generic_to_shared(&smBl[so]);
            cp_async4(dh, g_Bh + go, sz);
            cp_async4(dl, g_Bl + go, sz);
        }
        CP_COMMIT();
    };

    load_tile(0, 0);

    float acc[4][4][4];             // [m-frag][n-frag][c0..c3]
#pragma unroll
    for (int i = 0; i < 4; i++)
#pragma unroll
        for (int j = 0; j < 4; j++)
#pragma unroll
            for (int c = 0; c < 4; c++) acc[i][j][c] = 0.0f;

    for (int it = 0; it < NT_TILES; it++) {
        int p = it & 1;
        CP_WAIT0();
        __syncthreads();            // tile it landed; prior mma reads of Ah/Al done
        if (it + 1 < NT_TILES)
            load_tile(1 - p, (it + 1) * GBK);

        // block-wide A split: raw[p] -> Ah/Al (each element converted once)
#pragma unroll
        for (int u = 0; u < 8; u++) {
            int e = t + u * 256;
            int m = e >> 4, k = e & 15;
            float v = smAr[p * GBM * AST + m * AST + k];
            unsigned hi = f2tf32(v);
            smAh[m * AST + k] = hi;
            smAl[m * AST + k] = f2tf32(v - __uint_as_float(hi));
        }
        __syncthreads();

#pragma unroll
        for (int k8 = 0; k8 < GBK; k8 += 8) {
            // B fragments: direct hi/lo loads (no conversion)
            unsigned int bh[4][2], bl[4][2];
#pragma unroll
            for (int wn = 0; wn < 4; wn++) {
                int nloc = wN * 32 + wn * 8 + gid;
                int o0 = p * GBK * BST + (k8 + tig) * BST + nloc;
                int o1 = o0 + 4 * BST;
                bh[wn][0] = smBh[o0];  bh[wn][1] = smBh[o1];
                bl[wn][0] = smBl[o0];  bl[wn][1] = smBl[o1];
            }
#pragma unroll
            for (int wm = 0; wm < 4; wm++) {
                int mloc = wM * 64 + wm * 16 + gid;
                int a00 = mloc * AST + k8 + tig;
                int a10 = (mloc + 8) * AST + k8 + tig;
                unsigned int ah0 = smAh[a00],     ah1 = smAh[a10];
                unsigned int ah2 = smAh[a00 + 4], ah3 = smAh[a10 + 4];
                unsigned int al0 = smAl[a00],     al1 = smAl[a10];
                unsigned int al2 = smAl[a00 + 4], al3 = smAl[a10 + 4];
#pragma unroll
                for (int wn = 0; wn < 4; wn++) {
                    MMA_TF32(acc[wm][wn][0], acc[wm][wn][1], acc[wm][wn][2], acc[wm][wn][3],
                             ah0, ah1, ah2, ah3, bl[wn][0], bl[wn][1]);
                    MMA_TF32(acc[wm][wn][0], acc[wm][wn][1], acc[wm][wn][2], acc[wm][wn][3],
                             al0, al1, al2, al3, bh[wn][0], bh[wn][1]);
                    MMA_TF32(acc[wm][wn][0], acc[wm][wn][1], acc[wm][wn][2], acc[wm][wn][3],
                             ah0, ah1, ah2, ah3, bh[wn][0], bh[wn][1]);
                }
            }
        }
    }

    // fused epilogue: every compacted row is kept
#pragma unroll
    for (int wm = 0; wm < 4; wm++) {
#pragma unroll
        for (int half = 0; half < 2; half++) {       // c0/c1 (row) vs c2/c3 (row+8)
            int lm = wM * 64 + wm * 16 + gid + half * 8;
            int mi = m0 + lm;
            if (mi < cnt) {
                size_t rowoff = (size_t)rows_s[lm] * N;
#pragma unroll
                for (int wn = 0; wn < 4; wn++) {
                    int n = n0 + wN * 32 + wn * 8 + 2 * tig;
                    float v0 = acc[wm][wn][half * 2 + 0];
                    float v1 = acc[wm][wn][half * 2 + 1];
                    if (n < N)
                        out[rowoff + n]     = (v0 >= 0.25f) ? (v0 + 1.0f) * 0.5f : 0.0f;
                    if (n + 1 < N)
                        out[rowoff + n + 1] = (v1 >= 0.25f) ? (v1 + 1.0f) * 0.5f : 0.0f;
                }
            }
        }
    }
}

// ============================================================
extern "C" void kernel_launch(void* const* d_in, const int* in_sizes, int n_in,
                              void* d_out, int out_size)
{
    const float* human  = (const float*)d_in[0]; // [B,Q,2]
    const float* logits = (const float*)d_in[1]; // [B,Q,C]
    const float* bbox   = (const float*)d_in[2]; // [B,Q,4]
    const float* Aaug   = (const float*)d_in[3]; // [C,C]
    float* out = (float*)d_out;

    cudaFuncSetAttribute(nms_zero_kernel,
                         cudaFuncAttributeMaxDynamicSharedMemorySize, SB_TOTAL);
    cudaFuncSetAttribute(gemm_epi_kernel,
                         cudaFuncAttributeMaxDynamicSharedMemorySize, GB_TOTAL);

    // blocks [0,64): prep+NMS; [64,1088): zero scores; [1088,1349): split Aaug
    nms_zero_kernel<<<BATCH + ZBLK + CBLK, NMS_THREADS, SB_TOTAL>>>(human, bbox, Aaug, out);

    gemm_epi_kernel<<<dim3(3, NVCAP / GBM, BATCH), 256, GB_TOTAL>>>(logits, out);
}

// round 10
// speedup vs baseline: 1.2808x; 1.2808x over previous
#include <cuda_runtime.h>
#include <cuda_fp16.h>
#include <cstdint>
#include <math.h>

// Problem constants (fixed by the reference setup)
#define BATCH 64
#define QN    900
#define CN    365
#define MN    (BATCH * QN)          // 57600 rows

// Output layout in d_out (float32, tuple order: scores, boxes_int, keep)
#define OFF_BOX  (MN * CN)          // 21,024,000
#define OFF_KEEP (OFF_BOX + MN * 4) // 21,254,400

#define NVCAP 512                   // max valid entries per image (mean ~247, ~20 sigma margin)
#define MASKW 8                     // 512/64 suppression mask words

#define K2N   184                   // ceil(368/2) k-pairs stored for B (covers 23 k16-tiles)

// -------- device scratch (no allocations allowed, no per-replay reset needed) --------
__device__ int      g_rows[BATCH * NVCAP];  // per-batch kept row indices
__device__ int      g_cnt [BATCH];          // per-batch kept count
__device__ unsigned g_Bh2[K2N * CN];        // Aaug fp16-hi, k-pairs packed in half2
__device__ unsigned g_Bl2[K2N * CN];        // Aaug fp16-lo, k-pairs packed in half2

// ---- cp.async helpers (4-byte, src-size-0 form zero-fills out-of-bounds) ----
__device__ __forceinline__ void cp_async4(unsigned int dst_smem, const void* src, int szsrc) {
    asm volatile("cp.async.ca.shared.global [%0], [%1], 4, %2;\n"
                 :: "r"(dst_smem), "l"(src), "r"(szsrc));
}
#define CP_COMMIT() asm volatile("cp.async.commit_group;\n" ::: "memory")
#define CP_WAIT0()  asm volatile("cp.async.wait_group 0;\n" ::: "memory")

// ---- fp16 split helpers ----
__device__ __forceinline__ unsigned pack_h2(float a, float b) {
    __half2 h = __floats2half2_rn(a, b);          // low half = a
    return *reinterpret_cast<unsigned*>(&h);
}
__device__ __forceinline__ void split2(float a, float b, unsigned& hi, unsigned& lo) {
    __half ha = __float2half_rn(a), hb = __float2half_rn(b);
    float la = a - __half2float(ha), lb = b - __half2float(hb);
    __half2 h2 = __halves2half2(ha, hb);
    hi = *reinterpret_cast<unsigned*>(&h2);
    lo = pack_h2(la, lb);
}

#define MMA_F16(d0,d1,d2,d3, a0,a1,a2,a3, b0,b1)                           \
    asm volatile("mma.sync.aligned.m16n8k16.row.col.f32.f16.f16.f32 "      \
                 "{%0,%1,%2,%3}, {%4,%5,%6,%7}, {%8,%9}, {%0,%1,%2,%3};\n" \
                 : "+f"(d0), "+f"(d1), "+f"(d2), "+f"(d3)                  \
                 : "r"(a0), "r"(a1), "r"(a2), "r"(a3), "r"(b0), "r"(b1))

// ============================================================
// Kernel 1: blocks [0,64): per-image prep + NMS
//           blocks [64, 64+1024): zero the scores region
//           blocks [64+1024, ...): split Aaug into packed-half2 g_Bh2/g_Bl2
// ============================================================
#define NMS_THREADS 512
#define ZBLK 1024
#define CBLK 132                        // ceil(184*365 / 512)
// dynamic smem layout (bytes)
#define SB_BOXO  0                      // float4[900] : 14400
#define SB_SCORE 14400                  // float[900]  : 3600
#define SB_LIST  18000                  // int[512]    : 2048
#define SB_KEY   20048                  // float[512]  : 2048
#define SB_BOXS  22096                  // float4[512] : 8192
#define SB_MASK  30288                  // u64[512*8]  : 32768
#define SB_KP    63056                  // u8[512]     : 512
#define SB_CNT   63568                  // int         : 4
#define SB_TOTAL 63576

__global__ void __launch_bounds__(NMS_THREADS, 1)
nms_zero_kernel(const float* __restrict__ human,
                const float* __restrict__ bbox,
                const float* __restrict__ Aaug,
                float* __restrict__ out)
{
    int t = threadIdx.x;

    // ---------- Aaug fp16-split blocks (k-pair packed half2 layout) ----------
    if (blockIdx.x >= BATCH + ZBLK) {
        int i = (blockIdx.x - (BATCH + ZBLK)) * NMS_THREADS + t;
        if (i < K2N * CN) {
            int k2 = i / CN, n = i - k2 * CN;
            int k0 = 2 * k2, k1 = 2 * k2 + 1;
            float v0 = (k0 < CN) ? Aaug[k0 * CN + n] : 0.0f;
            float v1 = (k1 < CN) ? Aaug[k1 * CN + n] : 0.0f;
            unsigned hi, lo;
            split2(v0, v1, hi, lo);
            g_Bh2[i] = hi;
            g_Bl2[i] = lo;
        }
        return;
    }

    // ---------- zero-fill blocks ----------
    if (blockIdx.x >= BATCH) {
        const size_t total4 = (size_t)MN * CN / 4;
        float4 z = make_float4(0.f, 0.f, 0.f, 0.f);
        size_t stride = (size_t)ZBLK * NMS_THREADS;
        for (size_t p = (size_t)(blockIdx.x - BATCH) * NMS_THREADS + t;
             p < total4; p += stride)
            reinterpret_cast<float4*>(out)[p] = z;
        return;
    }

    // ---------- NMS blocks: one image each ----------
    extern __shared__ unsigned char sm[];
    float4*             sboxO  = (float4*)(sm + SB_BOXO);
    float*              sscore = (float*) (sm + SB_SCORE);
    int*                slist  = (int*)   (sm + SB_LIST);
    float*              skey   = (float*) (sm + SB_KEY);
    float4*             sboxS  = (float4*)(sm + SB_BOXS);
    unsigned long long* smask  = (unsigned long long*)(sm + SB_MASK);
    unsigned char*      skp    = sm + SB_KP;
    int*                scnt   = (int*)   (sm + SB_CNT);

    int b = blockIdx.x;
    int base = b * QN;
    float4* outBox4 = reinterpret_cast<float4*>(out + OFF_BOX);

    // Phase A: per-query prep
    if (t == 0) *scnt = 0;
    for (int q = t; q < QN; q += NMS_THREADS) {
        float2 h = reinterpret_cast<const float2*>(human)[base + q];
        float d = h.x - h.y;
        float p = 1.0f / (1.0f + expf(-fabsf(d)));   // max softmax prob
        bool valid = (d >= 0.0f) && (p >= 0.7f);     // label==0 && conf

        float4 bb = reinterpret_cast<const float4*>(bbox)[base + q];
        float x1 = (bb.x - 0.5f * bb.z) * 1333.0f;
        float y1 = (bb.y - 0.5f * bb.w) * 800.0f;
        float x2 = (bb.x + 0.5f * bb.z) * 1333.0f;
        float y2 = (bb.y + 0.5f * bb.w) * 800.0f;
        sboxO[q]  = make_float4(x1, y1, x2, y2);
        sscore[q] = valid ? p : -INFINITY;

        outBox4[base + q] = make_float4((float)(int)x1, (float)(int)y1,
                                        (float)(int)x2, (float)(int)y2);
        out[OFF_KEEP + base + q] = 0.0f;
    }
    __syncthreads();

    // Phase B: compact valid queries
    for (int q = t; q < QN; q += NMS_THREADS) {
        if (sscore[q] != -INFINITY) {
            int pos = atomicAdd(scnt, 1);
            if (pos < NVCAP) slist[pos] = q;
        }
    }
    __syncthreads();
    int nv = min(*scnt, NVCAP);

    // Phase C: bitonic sort (key desc, carry original q index)
    skey[t] = (t < nv) ? sscore[slist[t]] : -INFINITY;
    if (t >= nv) slist[t] = 0;
    skp[t] = 0;
    __syncthreads();
    for (int k = 2; k <= NVCAP; k <<= 1) {
        for (int j = k >> 1; j > 0; j >>= 1) {
            int ixj = t ^ j;
            if (ixj > t) {
                bool desc = ((t & k) == 0);
                float k1 = skey[t], k2 = skey[ixj];
                if (desc ? (k1 < k2) : (k1 > k2)) {
                    skey[t] = k2; skey[ixj] = k1;
                    int tmp = slist[t]; slist[t] = slist[ixj]; slist[ixj] = tmp;
                }
            }
            __syncthreads();
        }
    }

    // Phase D: gather boxes into sorted order
    if (t < nv) sboxS[t] = sboxO[slist[t]];
    __syncthreads();

    // Phase E: IoU suppression bitmask
    int nw = (nv + 63) >> 6;
    for (int flat = t; flat < nv * nw; flat += NMS_THREADS) {
        int i = flat / nw;
        int w = flat - i * nw;
        int jbase = w << 6;
        unsigned long long bits = 0ull;
        int jstart = max(jbase, i + 1);
        int jend   = min(jbase + 63, nv - 1);
        if (jstart <= jend) {
            float4 bi = sboxS[i];
            float areai = (bi.z - bi.x) * (bi.w - bi.y);
            for (int j = jstart; j <= jend; j++) {
                float4 bj = sboxS[j];
                float xx1 = fmaxf(bi.x, bj.x);
                float yy1 = fmaxf(bi.y, bj.y);
                float xx2 = fminf(bi.z, bj.z);
                float yy2 = fminf(bi.w, bj.w);
                float ww = fmaxf(xx2 - xx1, 0.0f);
                float hh = fmaxf(yy2 - yy1, 0.0f);
                float inter = ww * hh;
                float areaj = (bj.z - bj.x) * (bj.w - bj.y);
                float uni = fmaxf(areai + areaj - inter, 1e-9f);
                if (inter > 0.5f * uni) bits |= (1ull << (j - jbase));
            }
        }
        smask[i * MASKW + w] = bits;
    }
    __syncthreads();

    // Phase F: sequential greedy scan
    if (t < 32) {
        unsigned long long remv = 0ull;
        for (int i = 0; i < nv; i++) {
            unsigned long long word = __shfl_sync(0xffffffffu, remv, i >> 6);
            bool sup = (word >> (i & 63)) & 1ull;
            if (!sup) {
                if (t == 0) skp[i] = 1;
                if (t < nw) remv |= smask[i * MASKW + t];
            }
        }
    }
    __syncthreads();

    // Phase G: outputs
    if (t == 0) *scnt = 0;
    __syncthreads();
    if (t < nv && skp[t]) {
        out[OFF_KEEP + base + slist[t]] = 1.0f;
        int pos = atomicAdd(scnt, 1);
        g_rows[b * NVCAP + pos] = base + slist[t];
    }
    __syncthreads();
    if (t == 0) g_cnt[b] = *scnt;
}

// ============================================================
// Kernel 2: prob = logits[kept rows] @ Aaug via 2-way fp16 split,
// mma.sync.m16n8k16 (half the tensor instructions of 3xTF32 k8).
// A raw cp.async double-buffered + per-warp split; B pre-split packed half2.
// fused epilogue: scores = (prob>=0.25) ? (prob+1)*0.5 : 0
// ============================================================
#define GBM 128
#define GBN 128
#define GBK 16
#define ARST 20                     // raw A float k-stride
#define BST2 136                    // B half2 n-stride (rows offset by 8 banks)
#define NT_TILES 23                 // ceil(365/16)

__global__ void __launch_bounds__(256, 2)
gemm_epi_kernel(const float* __restrict__ A,   // [MN, 365]
                float* __restrict__ out)
{
    __shared__ __align__(16) float    Ar[2][GBM][ARST];   // raw A tiles
    __shared__ __align__(16) unsigned Bh[2][8][BST2];     // B hi, [k2][n] half2
    __shared__ __align__(16) unsigned Bl[2][8][BST2];     // B lo
    __shared__ int rows_s[GBM];

    const int K = CN, N = CN;
    int bz  = blockIdx.z;
    int cnt = g_cnt[bz];
    int m0  = blockIdx.y * GBM;
    if (m0 >= cnt) return;
    int n0 = blockIdx.x * GBN;

    int t    = threadIdx.x;
    int lane = t & 31;
    int gid  = lane >> 2;           // 0..7
    int tig  = lane & 3;            // 0..3
    int warp = t >> 5;
    int wM   = warp >> 2;           // 0..1  -> 64 m-rows each
    int wN   = warp & 3;            // 0..3  -> 32 n-cols each

    if (t < GBM) {
        int mi = m0 + t;
        rows_s[t] = g_rows[bz * NVCAP + (mi < cnt ? mi : cnt - 1)];
    }
    __syncthreads();

    // ---- async tile loader: raw A floats + pre-split packed-half2 B ----
    auto load_tile = [&](int buf, int it) {
        int k0 = it * GBK;
#pragma unroll
        for (int u = 0; u < 8; u++) {               // A: e -> (m=e>>4, k=e&15)
            int e = t + u * 256;
            int m = e >> 4, k = e & 15;
            int kk = k0 + k;
            int sz = (kk < K) ? 4 : 0;
            int kc = (kk < K) ? kk : (K - 1);
            unsigned int dst = (unsigned int)__cvta_generic_to_shared(&Ar[buf][m][k]);
            cp_async4(dst, A + (size_t)rows_s[m] * K + kc, sz);
        }
        int k20 = it * 8;                           // B: 8 k2-rows x 128 n
#pragma unroll
        for (int u = 0; u < 4; u++) {
            int e = t + u * 256;
            int k2 = e >> 7, n = e & 127;
            int nn = n0 + n;
            int sz = (nn < N) ? 4 : 0;
            int nc = (nn < N) ? nn : (N - 1);
            int go = (k20 + k2) * CN + nc;          // k20+k2 <= 183 always in-array
            unsigned int dh = (unsigned int)__cvta_generic_to_shared(&Bh[buf][k2][n]);
            unsigned int dl = (unsigned int)__cvta_generic_to_shared(&Bl[buf][k2][n]);
            cp_async4(dh, g_Bh2 + go, sz);
            cp_async4(dl, g_Bl2 + go, sz);
        }
        CP_COMMIT();
    };

    load_tile(0, 0);

    float acc[4][4][4];             // [m-frag][n-frag][c0..c3]
#pragma unroll
    for (int i = 0; i < 4; i++)
#pragma unroll
        for (int j = 0; j < 4; j++)
#pragma unroll
            for (int c = 0; c < 4; c++) acc[i][j][c] = 0.0f;

    for (int it = 0; it < NT_TILES; it++) {
        int p = it & 1;
        CP_WAIT0();
        __syncthreads();
        if (it + 1 < NT_TILES)
            load_tile(1 - p, it + 1);

        // B fragments: direct packed-half2 loads (b0: k2=tig, b1: k2=tig+4)
        unsigned bh[4][2], bl[4][2];
#pragma unroll
        for (int wn = 0; wn < 4; wn++) {
            int nloc = wN * 32 + wn * 8 + gid;
            bh[wn][0] = Bh[p][tig][nloc];
            bh[wn][1] = Bh[p][tig + 4][nloc];
            bl[wn][0] = Bl[p][tig][nloc];
            bl[wn][1] = Bl[p][tig + 4][nloc];
        }

#pragma unroll
        for (int wm = 0; wm < 4; wm++) {
            int r0 = wM * 64 + wm * 16 + gid;
            int r1 = r0 + 8;
            int c0 = 2 * tig, c2 = 2 * tig + 8;
            unsigned ah0, al0, ah1, al1, ah2, al2, ah3, al3;
            split2(Ar[p][r0][c0], Ar[p][r0][c0 + 1], ah0, al0);
            split2(Ar[p][r1][c0], Ar[p][r1][c0 + 1], ah1, al1);
            split2(Ar[p][r0][c2], Ar[p][r0][c2 + 1], ah2, al2);
            split2(Ar[p][r1][c2], Ar[p][r1][c2 + 1], ah3, al3);
#pragma unroll
            for (int wn = 0; wn < 4; wn++) {
                MMA_F16(acc[wm][wn][0], acc[wm][wn][1], acc[wm][wn][2], acc[wm][wn][3],
                        ah0, ah1, ah2, ah3, bl[wn][0], bl[wn][1]);
                MMA_F16(acc[wm][wn][0], acc[wm][wn][1], acc[wm][wn][2], acc[wm][wn][3],
                        al0, al1, al2, al3, bh[wn][0], bh[wn][1]);
                MMA_F16(acc[wm][wn][0], acc[wm][wn][1], acc[wm][wn][2], acc[wm][wn][3],
                        ah0, ah1, ah2, ah3, bh[wn][0], bh[wn][1]);
            }
        }
    }

    // fused epilogue: every compacted row is kept
#pragma unroll
    for (int wm = 0; wm < 4; wm++) {
#pragma unroll
        for (int half = 0; half < 2; half++) {       // c0/c1 (row) vs c2/c3 (row+8)
            int lm = wM * 64 + wm * 16 + gid + half * 8;
            int mi = m0 + lm;
            if (mi < cnt) {
                size_t rowoff = (size_t)rows_s[lm] * N;
#pragma unroll
                for (int wn = 0; wn < 4; wn++) {
                    int n = n0 + wN * 32 + wn * 8 + 2 * tig;
                    float v0 = acc[wm][wn][half * 2 + 0];
                    float v1 = acc[wm][wn][half * 2 + 1];
                    if (n < N)
                        out[rowoff + n]     = (v0 >= 0.25f) ? (v0 + 1.0f) * 0.5f : 0.0f;
                    if (n + 1 < N)
                        out[rowoff + n + 1] = (v1 >= 0.25f) ? (v1 + 1.0f) * 0.5f : 0.0f;
                }
            }
        }
    }
}

// ============================================================
extern "C" void kernel_launch(void* const* d_in, const int* in_sizes, int n_in,
                              void* d_out, int out_size)
{
    const float* human  = (const float*)d_in[0]; // [B,Q,2]
    const float* logits = (const float*)d_in[1]; // [B,Q,C]
    const float* bbox   = (const float*)d_in[2]; // [B,Q,4]
    const float* Aaug   = (const float*)d_in[3]; // [C,C]
    float* out = (float*)d_out;

    cudaFuncSetAttribute(nms_zero_kernel,
                         cudaFuncAttributeMaxDynamicSharedMemorySize, SB_TOTAL);

    // blocks [0,64): prep+NMS; [64,1088): zero scores; [1088,1220): split Aaug
    nms_zero_kernel<<<BATCH + ZBLK + CBLK, NMS_THREADS, SB_TOTAL>>>(human, bbox, Aaug, out);

    gemm_epi_kernel<<<dim3(3, NVCAP / GBM, BATCH), 256>>>(logits, out);
}